// round 1
// baseline (speedup 1.0000x reference)
#include <cuda_runtime.h>
#include <cstdint>

#define B_ 32
#define T_ 2048
#define D_ 512
#define U_ 512

// Scratch for the input projection XK = x @ W  (134 MB, static __device__ — no allocation).
__device__ float g_xk[(size_t)B_ * T_ * U_];

typedef unsigned long long ull;

// ---- packed f32x2 helpers (sm_103a) ----
__device__ __forceinline__ ull pack2(float lo, float hi) {
    ull r;
    asm("mov.b64 %0, {%1, %2};" : "=l"(r) : "f"(lo), "f"(hi));
    return r;
}
__device__ __forceinline__ void fma2(ull &d, ull a, ull b) {
    asm("fma.rn.f32x2 %0, %1, %2, %0;" : "+l"(d) : "l"(a), "l"(b));
}
__device__ __forceinline__ void unpack2(ull v, float &lo, float &hi) {
    asm("mov.b64 {%0, %1}, %2;" : "=f"(lo), "=f"(hi) : "l"(v));
}

// ============================================================================
// Phase 1: XK = x @ W.   A:[65536,512] row-major, B:[512,512] row-major,
// C=g_xk:[65536,512]. 128x128 tile, K-tile 16, 256 threads, 8x8 micro-tile,
// f32x2 packed FMA, double-buffered smem.
// ============================================================================
__global__ void __launch_bounds__(256, 2)
gemm_xk(const float* __restrict__ A, const float* __restrict__ Bm) {
    __shared__ __align__(16) float As[2][16][132];  // [k][m], padded stride 132 (528B, 16B-aligned)
    __shared__ __align__(16) float Bs[2][16][128];  // [k][n]

    const int tid = threadIdx.x;
    const int m0 = blockIdx.y * 128;
    const int n0 = blockIdx.x * 128;
    const int tx = tid & 15;   // n direction
    const int ty = tid >> 4;   // m direction

    ull acc[8][4];
    #pragma unroll
    for (int i = 0; i < 8; i++)
        #pragma unroll
        for (int j = 0; j < 4; j++) acc[i][j] = 0ull;  // bit pattern 0 == (+0.f, +0.f)

    float4 ra[2], rb[2];

    // ---- global loads for K-tile kt into registers ----
    auto gload = [&](int kt) {
        #pragma unroll
        for (int i = 0; i < 2; i++) {
            int f = tid * 2 + i;              // 0..511
            int m = f >> 2, kq = f & 3;
            ra[i] = *(const float4*)(A + (size_t)(m0 + m) * D_ + kt + kq * 4);
        }
        #pragma unroll
        for (int i = 0; i < 2; i++) {
            int f = tid + (i << 8);           // 0..511
            int k = f >> 5, nq = f & 31;
            rb[i] = *(const float4*)(Bm + (size_t)(kt + k) * U_ + n0 + nq * 4);
        }
    };
    // ---- registers -> smem buffer s ----
    auto sstore = [&](int s) {
        #pragma unroll
        for (int i = 0; i < 2; i++) {
            int f = tid * 2 + i;
            int m = f >> 2, kq = f & 3;
            As[s][kq * 4 + 0][m] = ra[i].x;
            As[s][kq * 4 + 1][m] = ra[i].y;
            As[s][kq * 4 + 2][m] = ra[i].z;
            As[s][kq * 4 + 3][m] = ra[i].w;
        }
        #pragma unroll
        for (int i = 0; i < 2; i++) {
            int f = tid + (i << 8);
            int k = f >> 5, nq = f & 31;
            *(float4*)&Bs[s][k][nq * 4] = rb[i];
        }
    };

    gload(0);
    sstore(0);
    __syncthreads();

    int s = 0;
    for (int kt = 0; kt < D_; kt += 16) {
        const bool more = (kt + 16) < D_;
        if (more) gload(kt + 16);

        #pragma unroll
        for (int kk = 0; kk < 16; kk++) {
            float a[8];
            float4 a40 = *(const float4*)&As[s][kk][ty * 8];
            float4 a41 = *(const float4*)&As[s][kk][ty * 8 + 4];
            a[0] = a40.x; a[1] = a40.y; a[2] = a40.z; a[3] = a40.w;
            a[4] = a41.x; a[5] = a41.y; a[6] = a41.z; a[7] = a41.w;
            ull ap[8];
            #pragma unroll
            for (int i = 0; i < 8; i++) ap[i] = pack2(a[i], a[i]);
            ull bp[4];
            #pragma unroll
            for (int j = 0; j < 4; j++)
                bp[j] = *(const ull*)&Bs[s][kk][tx * 8 + j * 2];
            #pragma unroll
            for (int i = 0; i < 8; i++)
                #pragma unroll
                for (int j = 0; j < 4; j++) fma2(acc[i][j], ap[i], bp[j]);
        }

        if (more) sstore(s ^ 1);
        __syncthreads();
        s ^= 1;
    }

    // store C (g_xk)
    #pragma unroll
    for (int i = 0; i < 8; i++) {
        float lo0, hi0, lo1, hi1, lo2v, hi2v, lo3, hi3;
        unpack2(acc[i][0], lo0, hi0);
        unpack2(acc[i][1], lo1, hi1);
        unpack2(acc[i][2], lo2v, hi2v);
        unpack2(acc[i][3], lo3, hi3);
        float4 v0 = make_float4(lo0, hi0, lo1, hi1);
        float4 v1 = make_float4(lo2v, hi2v, lo3, hi3);
        float* cptr = g_xk + (size_t)(m0 + ty * 8 + i) * U_ + n0 + tx * 8;
        *(float4*)(cptr) = v0;
        *(float4*)(cptr + 4) = v1;
    }
}

// ============================================================================
// Phase 2: linear scan  h_t = xk_t + h_{t-1} @ R.
// 16 clusters (one per 2 batches) x 8 CTAs (one per 64-wide u-slice) = 128 CTAs,
// exactly one wave. R slice resident in registers (32 x f32x2 per thread).
// h state in smem, parity double-buffered; new h pushed to all cluster peers
// via mapa + st.shared::cluster; one barrier.cluster per step.
// ============================================================================
__global__ void __cluster_dims__(8, 1, 1) __launch_bounds__(512, 1)
scan_kernel(const float* __restrict__ R, float* __restrict__ out) {
    __shared__ __align__(16) float hbuf[2][2][U_];   // [parity][batch][k]   8 KB
    __shared__ __align__(16) float part[8][2][64];   // [kg][batch][u]       4 KB

    const int tid = threadIdx.x;
    const int uu = tid & 63;        // u within slice
    const int kg = tid >> 6;        // 0..7, k-group of 64
    const int k0 = kg * 64;

    uint32_t rank;
    asm("mov.u32 %0, %%cluster_ctarank;" : "=r"(rank));
    const int cid = blockIdx.x >> 3;     // cluster id = batch pair
    const int b0 = cid * 2;
    const int ug = (int)rank * 64 + uu;  // global u of this thread's R column

    // ---- load R slice into registers: rp[j] = (R[k0+2j][ug], R[k0+2j+1][ug]) ----
    ull rp[32];
    #pragma unroll
    for (int j = 0; j < 32; j++) {
        int k = k0 + 2 * j;
        rp[j] = pack2(R[(size_t)k * U_ + ug], R[(size_t)(k + 1) * U_ + ug]);
    }

    // ---- zero h_0 (parity 0) ----
    for (int i = tid; i < 2 * U_; i += 512) hbuf[0][0][i] = 0.f;
    __syncthreads();
    asm volatile("barrier.cluster.arrive.aligned;" ::: "memory");
    asm volatile("barrier.cluster.wait.aligned;" ::: "memory");

    const bool is_writer = (tid < 128);
    const int wb = (tid >> 6) & 1;  // writer batch (0/1)
    const int wu = tid & 63;        // writer u within slice
    const int wug = (int)rank * 64 + wu;
    float* out_base = out + ((size_t)(b0 + wb) * T_) * U_ + wug;
    const float* xk_base = g_xk + ((size_t)(b0 + wb) * T_) * U_ + wug;
    const uint32_t haddr_base = (uint32_t)__cvta_generic_to_shared(&hbuf[0][0][0]);

    for (int t = 0; t < T_; t++) {
        const int p = t & 1;

        // prefetch this step's xk early (latency hidden under the FMA loop)
        float xkv = 0.f;
        if (is_writer) xkv = __ldg(xk_base + (size_t)t * U_);

        // ---- partial dot products: acc_b = sum_k h[b][k] * R[k][ug] over k0..k0+63 ----
        const float* h0 = &hbuf[p][0][k0];
        const float* h1 = &hbuf[p][1][k0];
        ull acc0 = 0ull, acc1 = 0ull;
        #pragma unroll
        for (int j = 0; j < 32; j++) {
            ull hp = *(const ull*)(h0 + 2 * j);
            fma2(acc0, hp, rp[j]);
        }
        #pragma unroll
        for (int j = 0; j < 32; j++) {
            ull hp = *(const ull*)(h1 + 2 * j);
            fma2(acc1, hp, rp[j]);
        }
        float a0x, a0y, a1x, a1y;
        unpack2(acc0, a0x, a0y);
        unpack2(acc1, a1x, a1y);
        part[kg][0][uu] = a0x + a0y;
        part[kg][1][uu] = a1x + a1y;
        __syncthreads();

        if (is_writer) {
            float sum = xkv;
            #pragma unroll
            for (int g = 0; g < 8; g++) sum += part[g][wb][wu];
            // output h_t
            out_base[(size_t)t * U_] = sum;
            // push into every cluster CTA's hbuf[p^1][wb][wug]
            uint32_t laddr = haddr_base +
                (uint32_t)(((((p ^ 1) * 2 + wb) * U_) + wug) * 4);
            #pragma unroll
            for (uint32_t r = 0; r < 8; r++) {
                uint32_t raddr;
                asm volatile("mapa.shared::cluster.u32 %0, %1, %2;"
                             : "=r"(raddr) : "r"(laddr), "r"(r));
                asm volatile("st.shared::cluster.f32 [%0], %1;"
                             :: "r"(raddr), "f"(sum) : "memory");
            }
        }

        // one cluster barrier per step: releases our pushes, orders peer reads
        asm volatile("barrier.cluster.arrive.aligned;" ::: "memory");
        asm volatile("barrier.cluster.wait.aligned;" ::: "memory");
    }
}

// ============================================================================
// launch
// ============================================================================
extern "C" void kernel_launch(void* const* d_in, const int* in_sizes, int n_in,
                              void* d_out, int out_size) {
    const float* x = (const float*)d_in[0];   // [32, 2048, 512]
    const float* W = (const float*)d_in[1];   // [512, 512]
    const float* R = (const float*)d_in[2];   // [512, 512]
    float* out = (float*)d_out;               // [32, 2048, 512]

    dim3 g1(U_ / 128, (B_ * T_) / 128);       // (4, 512)
    gemm_xk<<<g1, 256>>>(x, W);
    scan_kernel<<<128, 512>>>(R, out);
}

// round 2
// speedup vs baseline: 1.3205x; 1.3205x over previous
#include <cuda_runtime.h>
#include <cstdint>

#define B_ 32
#define T_ 2048
#define D_ 512
#define U_ 512

// Scratch for the input projection XK = x @ W  (134 MB, static __device__ — no allocation).
__device__ float g_xk[(size_t)B_ * T_ * U_];

typedef unsigned long long ull;

// ---- packed f32x2 helpers (sm_103a) ----
__device__ __forceinline__ ull pack2(float lo, float hi) {
    ull r;
    asm("mov.b64 %0, {%1, %2};" : "=l"(r) : "f"(lo), "f"(hi));
    return r;
}
__device__ __forceinline__ void fma2(ull &d, ull a, ull b) {
    asm("fma.rn.f32x2 %0, %1, %2, %0;" : "+l"(d) : "l"(a), "l"(b));
}
__device__ __forceinline__ void add2(ull &d, ull a) {
    asm("add.rn.f32x2 %0, %0, %1;" : "+l"(d) : "l"(a));
}
__device__ __forceinline__ void unpack2(ull v, float &lo, float &hi) {
    asm("mov.b64 {%0, %1}, %2;" : "=f"(lo), "=f"(hi) : "l"(v));
}

// ============================================================================
// Phase 1: XK = x @ W.  (unchanged from R1 — ~0.86ms, ~40 TF/s fp32)
// ============================================================================
__global__ void __launch_bounds__(256, 2)
gemm_xk(const float* __restrict__ A, const float* __restrict__ Bm) {
    __shared__ __align__(16) float As[2][16][132];
    __shared__ __align__(16) float Bs[2][16][128];

    const int tid = threadIdx.x;
    const int m0 = blockIdx.y * 128;
    const int n0 = blockIdx.x * 128;
    const int tx = tid & 15;
    const int ty = tid >> 4;

    ull acc[8][4];
    #pragma unroll
    for (int i = 0; i < 8; i++)
        #pragma unroll
        for (int j = 0; j < 4; j++) acc[i][j] = 0ull;

    float4 ra[2], rb[2];

    auto gload = [&](int kt) {
        #pragma unroll
        for (int i = 0; i < 2; i++) {
            int f = tid * 2 + i;
            int m = f >> 2, kq = f & 3;
            ra[i] = *(const float4*)(A + (size_t)(m0 + m) * D_ + kt + kq * 4);
        }
        #pragma unroll
        for (int i = 0; i < 2; i++) {
            int f = tid + (i << 8);
            int k = f >> 5, nq = f & 31;
            rb[i] = *(const float4*)(Bm + (size_t)(kt + k) * U_ + n0 + nq * 4);
        }
    };
    auto sstore = [&](int s) {
        #pragma unroll
        for (int i = 0; i < 2; i++) {
            int f = tid * 2 + i;
            int m = f >> 2, kq = f & 3;
            As[s][kq * 4 + 0][m] = ra[i].x;
            As[s][kq * 4 + 1][m] = ra[i].y;
            As[s][kq * 4 + 2][m] = ra[i].z;
            As[s][kq * 4 + 3][m] = ra[i].w;
        }
        #pragma unroll
        for (int i = 0; i < 2; i++) {
            int f = tid + (i << 8);
            int k = f >> 5, nq = f & 31;
            *(float4*)&Bs[s][k][nq * 4] = rb[i];
        }
    };

    gload(0);
    sstore(0);
    __syncthreads();

    int s = 0;
    for (int kt = 0; kt < D_; kt += 16) {
        const bool more = (kt + 16) < D_;
        if (more) gload(kt + 16);

        #pragma unroll
        for (int kk = 0; kk < 16; kk++) {
            float a[8];
            float4 a40 = *(const float4*)&As[s][kk][ty * 8];
            float4 a41 = *(const float4*)&As[s][kk][ty * 8 + 4];
            a[0] = a40.x; a[1] = a40.y; a[2] = a40.z; a[3] = a40.w;
            a[4] = a41.x; a[5] = a41.y; a[6] = a41.z; a[7] = a41.w;
            ull ap[8];
            #pragma unroll
            for (int i = 0; i < 8; i++) ap[i] = pack2(a[i], a[i]);
            ull bp[4];
            #pragma unroll
            for (int j = 0; j < 4; j++)
                bp[j] = *(const ull*)&Bs[s][kk][tx * 8 + j * 2];
            #pragma unroll
            for (int i = 0; i < 8; i++)
                #pragma unroll
                for (int j = 0; j < 4; j++) fma2(acc[i][j], ap[i], bp[j]);
        }

        if (more) sstore(s ^ 1);
        __syncthreads();
        s ^= 1;
    }

    #pragma unroll
    for (int i = 0; i < 8; i++) {
        float lo0, hi0, lo1, hi1, lo2v, hi2v, lo3, hi3;
        unpack2(acc[i][0], lo0, hi0);
        unpack2(acc[i][1], lo1, hi1);
        unpack2(acc[i][2], lo2v, hi2v);
        unpack2(acc[i][3], lo3, hi3);
        float4 v0 = make_float4(lo0, hi0, lo1, hi1);
        float4 v1 = make_float4(lo2v, hi2v, lo3, hi3);
        float* cptr = g_xk + (size_t)(m0 + ty * 8 + i) * U_ + n0 + tx * 8;
        *(float4*)(cptr) = v0;
        *(float4*)(cptr + 4) = v1;
    }
}

// ============================================================================
// Phase 2: linear scan  h_t = xk_t + h_{t-1} @ R.
// 16 clusters x 8 CTAs. R slice in registers. Per-step sync is now a
// transaction mbarrier fed by st.async (no cluster barrier, no L1 flush).
// ============================================================================

// Incoming bytes per CTA per step: 8 source CTAs x 64 b64 pairs = 4096 B.
#define STEP_TX_BYTES 4096u

__device__ __forceinline__ void mbar_init(uint32_t addr, uint32_t count) {
    asm volatile("mbarrier.init.shared.b64 [%0], %1;" :: "r"(addr), "r"(count) : "memory");
}
__device__ __forceinline__ void mbar_arrive_expect_tx(uint32_t addr, uint32_t bytes) {
    asm volatile("mbarrier.arrive.expect_tx.shared.b64 _, [%0], %1;"
                 :: "r"(addr), "r"(bytes) : "memory");
}
__device__ __forceinline__ void mbar_wait_parity_acq_cluster(uint32_t addr, uint32_t ph) {
    uint32_t done;
    asm volatile(
        "{\n\t.reg .pred p;\n\t"
        "mbarrier.try_wait.parity.acquire.cluster.shared::cta.b64 p, [%1], %2;\n\t"
        "selp.b32 %0, 1, 0, p;\n\t}"
        : "=r"(done) : "r"(addr), "r"(ph) : "memory");
    if (!done) {
        asm volatile(
            "{\n\t.reg .pred P1;\n\t"
            "WL_%=:\n\t"
            "mbarrier.try_wait.parity.acquire.cluster.shared::cta.b64 P1, [%0], %1, 0x989680;\n\t"
            "@P1 bra.uni WD_%=;\n\t"
            "bra.uni WL_%=;\n\t"
            "WD_%=:\n\t}"
            :: "r"(addr), "r"(ph) : "memory");
    }
}
__device__ __forceinline__ void st_async_b64(uint32_t daddr, ull val, uint32_t maddr) {
    asm volatile(
        "st.async.shared::cluster.mbarrier::complete_tx::bytes.b64 [%0], %1, [%2];"
        :: "r"(daddr), "l"(val), "r"(maddr) : "memory");
}

__global__ void __cluster_dims__(8, 1, 1) __launch_bounds__(512, 1)
scan_kernel(const float* __restrict__ R, float* __restrict__ out) {
    __shared__ __align__(16) float hbuf[2][2][U_];   // [parity][batch][k]   8 KB
    __shared__ __align__(16) float part[8][2][64];   // [kg][batch][u]       4 KB
    __shared__ __align__(8)  ull  mbar[2];           // full-barrier per parity

    const int tid = threadIdx.x;
    const int uu = tid & 63;
    const int kg = tid >> 6;
    const int k0 = kg * 64;

    uint32_t rank;
    asm("mov.u32 %0, %%cluster_ctarank;" : "=r"(rank));
    const int cid = blockIdx.x >> 3;
    const int b0 = cid * 2;
    const int ug = (int)rank * 64 + uu;

    // ---- R slice in registers: rp[j] = (R[k0+2j][ug], R[k0+2j+1][ug]) ----
    ull rp[32];
    #pragma unroll
    for (int j = 0; j < 32; j++) {
        int k = k0 + 2 * j;
        rp[j] = pack2(R[(size_t)k * U_ + ug], R[(size_t)(k + 1) * U_ + ug]);
    }

    // ---- init: mbarriers + h_0 = 0 ----
    const uint32_t hbase = (uint32_t)__cvta_generic_to_shared(&hbuf[0][0][0]);
    const uint32_t mbase = (uint32_t)__cvta_generic_to_shared(&mbar[0]);
    const uint32_t mdelta = mbase - hbase;

    if (tid == 0) {
        mbar_init(mbase, 1);
        mbar_init(mbase + 8, 1);
    }
    for (int i = tid; i < 2 * U_; i += 512) hbuf[0][0][i] = 0.f;
    __syncthreads();
    // make peer mbarrier init visible before any st.async targets it
    asm volatile("barrier.cluster.arrive.aligned;" ::: "memory");
    asm volatile("barrier.cluster.wait.aligned;" ::: "memory");

    // ---- writer setup: 64 writers, each owns a (batch, column-pair) ----
    const bool is_writer = (tid < 64);
    const int wb = tid >> 5;            // writer batch 0/1
    const int wp = tid & 31;            // pair index within slice
    const int wug = (int)rank * 64 + 2 * wp;
    float* out_base = out + ((size_t)(b0 + wb) * T_) * U_ + wug;
    const float* xk_base = g_xk + ((size_t)(b0 + wb) * T_) * U_ + wug;

    // remote smem base per rank (mapa is affine within a CTA's window)
    uint32_t rb[8];
    #pragma unroll
    for (uint32_t r = 0; r < 8; r++) {
        asm volatile("mapa.shared::cluster.u32 %0, %1, %2;"
                     : "=r"(rb[r]) : "r"(hbase), "r"(r));
    }

    int ph0 = 0, ph1 = 0;

    for (int t = 0; t < T_; t++) {
        const int p = t & 1;

        // prefetch xk[t] before the wait (no dependency on h state)
        float2 xk2 = make_float2(0.f, 0.f);
        if (is_writer) xk2 = *(const float2*)(xk_base + (size_t)t * U_);

        // wait for h state of this step (hbuf[p]); t=0 state is local zeros
        if (t > 0) {
            if (p) { mbar_wait_parity_acq_cluster(mbase + 8, (uint32_t)ph1); ph1 ^= 1; }
            else   { mbar_wait_parity_acq_cluster(mbase,     (uint32_t)ph0); ph0 ^= 1; }
        }

        // arm the other parity's barrier for its next use
        if (tid == 0 && t < T_ - 1) {
            mbar_arrive_expect_tx(mbase + (uint32_t)(p ^ 1) * 8, STEP_TX_BYTES);
        }

        // ---- partial dot products over this CTA's 64-k slice ----
        const ull* h0 = (const ull*)&hbuf[p][0][k0];
        const ull* h1 = (const ull*)&hbuf[p][1][k0];
        ull a0a = 0ull, a0b = 0ull, a1a = 0ull, a1b = 0ull;
        #pragma unroll
        for (int j = 0; j < 32; j += 2) {
            fma2(a0a, h0[j],     rp[j]);
            fma2(a0b, h0[j + 1], rp[j + 1]);
        }
        #pragma unroll
        for (int j = 0; j < 32; j += 2) {
            fma2(a1a, h1[j],     rp[j]);
            fma2(a1b, h1[j + 1], rp[j + 1]);
        }
        add2(a0a, a0b);
        add2(a1a, a1b);
        float x0, y0, x1, y1;
        unpack2(a0a, x0, y0);
        unpack2(a1a, x1, y1);
        part[kg][0][uu] = x0 + y0;
        part[kg][1][uu] = x1 + y1;
        __syncthreads();

        if (is_writer) {
            // reduce 8 kg-partials for 2 adjacent columns, packed
            ull sum = pack2(xk2.x, xk2.y);
            #pragma unroll
            for (int g = 0; g < 8; g++)
                add2(sum, *(const ull*)&part[g][wb][2 * wp]);

            // output h_t
            float lo, hi;
            unpack2(sum, lo, hi);
            *(float2*)(out_base + (size_t)t * U_) = make_float2(lo, hi);

            // push new state into every cluster CTA's hbuf[p^1] with tx credit
            if (t < T_ - 1) {
                const uint32_t doff =
                    (uint32_t)((((p ^ 1) * 2 + wb) * U_ + wug) * 4);
                const uint32_t moff = mdelta + (uint32_t)(p ^ 1) * 8;
                #pragma unroll
                for (uint32_t r = 0; r < 8; r++) {
                    st_async_b64(rb[r] + doff, sum, rb[r] + moff);
                }
            }
        }
        // no trailing barrier: next-step hazards are ordered through the
        // self-inclusive st.async -> mbarrier completion chain.
    }

    // do not exit while peers' in-flight st.async may target our smem
    asm volatile("barrier.cluster.arrive.aligned;" ::: "memory");
    asm volatile("barrier.cluster.wait.aligned;" ::: "memory");
}

// ============================================================================
// launch
// ============================================================================
extern "C" void kernel_launch(void* const* d_in, const int* in_sizes, int n_in,
                              void* d_out, int out_size) {
    const float* x = (const float*)d_in[0];   // [32, 2048, 512]
    const float* W = (const float*)d_in[1];   // [512, 512]
    const float* R = (const float*)d_in[2];   // [512, 512]
    float* out = (float*)d_out;               // [32, 2048, 512]

    dim3 g1(U_ / 128, (B_ * T_) / 128);       // (4, 512)
    gemm_xk<<<g1, 256>>>(x, W);
    scan_kernel<<<128, 512>>>(R, out);
}